// round 1
// baseline (speedup 1.0000x reference)
#include <cuda_runtime.h>
#include <cstdint>

// Problem constants (fixed by the dataset)
#define B_     8192
#define NSITE  256
#define D_     128
#define OUT_   10

// --------------------------------------------------------------------------
// Scratch: static device globals (no allocation allowed in kernel_launch).
//   g_cos/g_sin: feature map, SITE-MAJOR [site][b] for coalesced step reads.
//   g_left:      ping-pong state buffers [2][B][D].
// --------------------------------------------------------------------------
__device__ float g_cos[NSITE * B_];          // 8 MB
__device__ float g_sin[NSITE * B_];          // 8 MB
__device__ float g_left[2][B_ * D_];         // 8 MB

// ==========================================================================
// Kernel 1: feature map. One warp per sample: min/max over 256 features,
// then phi = (cos(pi/2*xn), sin(pi/2*xn)) via precise sincospif.
// ==========================================================================
__global__ void phi_kernel(const float* __restrict__ x) {
    int warp = (blockIdx.x * blockDim.x + threadIdx.x) >> 5;
    int lane = threadIdx.x & 31;
    if (warp >= B_) return;
    const float* xr = x + (size_t)warp * NSITE;

    float v[8];
    float mn = 3.402823466e38f, mx = -3.402823466e38f;
#pragma unroll
    for (int i = 0; i < 8; i++) {
        v[i] = xr[lane + i * 32];
        mn = fminf(mn, v[i]);
        mx = fmaxf(mx, v[i]);
    }
#pragma unroll
    for (int o = 16; o; o >>= 1) {
        mn = fminf(mn, __shfl_xor_sync(0xffffffffu, mn, o));
        mx = fmaxf(mx, __shfl_xor_sync(0xffffffffu, mx, o));
    }
    float denom = mx - mn + 1e-6f;

#pragma unroll
    for (int i = 0; i < 8; i++) {
        float xn = (v[i] - mn) / denom;          // in [0,1]
        float s, c;
        sincospif(0.5f * xn, &s, &c);            // sin/cos(pi/2 * xn), precise
        int site = lane + i * 32;
        g_cos[(size_t)site * B_ + warp] = c;
        g_sin[(size_t)site * B_ + warp] = s;
    }
}

// ==========================================================================
// Kernel 2: initial state. left0[b,r] = first[0,r]*cos0[b] + first[1,r]*sin0[b]
// first layout (1,2,D): element [0,d,r] at d*D + r.
// ==========================================================================
__global__ void left0_kernel(const float* __restrict__ first) {
    int b = blockIdx.x;
    int r = threadIdx.x;
    float c = g_cos[b];     // site 0
    float s = g_sin[b];
    g_left[0][(size_t)b * D_ + r] = first[r] * c + first[D_ + r] * s;
}

// ==========================================================================
// Kernel 3: one MPS step as a GEMM.
//   A[b, 2l+d] = phi_d[b] * left[b,l]   (built into smem on the fly)
//   left'[b, r] = sum_k A[b,k] * mid[m][k, r]   (mid[m] viewed as [256,128])
// CTA tile: BM=128 rows x BN=64 cols, K=256 fully resident in smem.
//   smem: As [128][260] (pad keeps float4 alignment) + Ms [256][64] = 194 KB
// 256 threads, each computes an 8x4 micro-tile. FFMA-bound by design.
// ==========================================================================
#define AS_LD 260
#define STEP_SMEM_BYTES ((128 * AS_LD + 256 * 64) * 4)

__global__ __launch_bounds__(256, 1)
void step_kernel(const float* __restrict__ mid, int m, int cur) {
    extern __shared__ float smem[];
    float* As = smem;                    // [128][AS_LD]
    float* Ms = smem + 128 * AS_LD;      // [256][64]

    const int r0 = blockIdx.x * 128;     // sample tile
    const int c0 = blockIdx.y * 64;      // output-column tile

    const float* left_in  = g_left[cur];
    float*       left_out = g_left[cur ^ 1];
    const float* cosp = g_cos + (size_t)(m + 1) * B_;   // phi site = m+1
    const float* sinp = g_sin + (size_t)(m + 1) * B_;
    // mid[m, l, d, r] at m*2*D*D + (2l+d)*D + r  -> [256,128] row-major slice
    const float* midp = mid + (size_t)m * (2 * D_ * D_) + c0;

    // ---- Build A tile: fold cos/sin into left, interleaved over d ----
    for (int t = threadIdx.x; t < 128 * 32; t += 256) {
        int r  = t >> 5;
        int l4 = t & 31;
        int b  = r0 + r;
        float c = cosp[b];
        float s = sinp[b];
        float4 L = *(const float4*)&left_in[(size_t)b * D_ + l4 * 4];
        float4 e0 = make_float4(c * L.x, s * L.x, c * L.y, s * L.y);
        float4 e1 = make_float4(c * L.z, s * L.z, c * L.w, s * L.w);
        float* dst = &As[r * AS_LD + l4 * 8];
        *(float4*)(dst)     = e0;
        *(float4*)(dst + 4) = e1;
    }
    // ---- Load M slice [256 x 64] ----
    for (int t = threadIdx.x; t < 256 * 16; t += 256) {
        int k  = t >> 4;
        int c4 = t & 15;
        *(float4*)&Ms[k * 64 + c4 * 4] =
            *(const float4*)&midp[(size_t)k * D_ + c4 * 4];
    }
    __syncthreads();

    // ---- Compute 8x4 micro-tile per thread over K=256 ----
    const int tx = threadIdx.x & 15;   // col group: cols tx*4 .. tx*4+3
    const int ty = threadIdx.x >> 4;   // row group: rows ty*8 .. ty*8+7

    float acc[8][4];
#pragma unroll
    for (int i = 0; i < 8; i++)
#pragma unroll
        for (int j = 0; j < 4; j++) acc[i][j] = 0.0f;

    const float* a_base = &As[(ty * 8) * AS_LD];
    const float* b_base = &Ms[tx * 4];

#pragma unroll 2
    for (int k = 0; k < 256; k += 4) {
        float4 b0 = *(const float4*)&b_base[(k + 0) * 64];
        float4 b1 = *(const float4*)&b_base[(k + 1) * 64];
        float4 b2 = *(const float4*)&b_base[(k + 2) * 64];
        float4 b3 = *(const float4*)&b_base[(k + 3) * 64];
#pragma unroll
        for (int i = 0; i < 8; i++) {
            float4 a = *(const float4*)&a_base[i * AS_LD + k];
            acc[i][0] += a.x * b0.x; acc[i][1] += a.x * b0.y;
            acc[i][2] += a.x * b0.z; acc[i][3] += a.x * b0.w;
            acc[i][0] += a.y * b1.x; acc[i][1] += a.y * b1.y;
            acc[i][2] += a.y * b1.z; acc[i][3] += a.y * b1.w;
            acc[i][0] += a.z * b2.x; acc[i][1] += a.z * b2.y;
            acc[i][2] += a.z * b2.z; acc[i][3] += a.z * b2.w;
            acc[i][0] += a.w * b3.x; acc[i][1] += a.w * b3.y;
            acc[i][2] += a.w * b3.z; acc[i][3] += a.w * b3.w;
        }
    }

    // ---- Write output tile ----
#pragma unroll
    for (int i = 0; i < 8; i++) {
        int b = r0 + ty * 8 + i;
        *(float4*)&left_out[(size_t)b * D_ + c0 + tx * 4] =
            make_float4(acc[i][0], acc[i][1], acc[i][2], acc[i][3]);
    }
}

// ==========================================================================
// Kernel 4: final contraction + linear head. One warp per sample.
//   scalar[b] = sum_l left[b,l] * (last[l,0]*cosN + last[l,1]*sinN)
//   out[b,o]  = scalar[b] * w[o] + bias[o]
// last layout (D,2,1): [l,d] at 2l+d.  w layout (OUT,1): w[o].
// ==========================================================================
__global__ void final_kernel(const float* __restrict__ last,
                             const float* __restrict__ w,
                             const float* __restrict__ bias,
                             float* __restrict__ out, int cur) {
    int warp = (blockIdx.x * blockDim.x + threadIdx.x) >> 5;
    int lane = threadIdx.x & 31;
    if (warp >= B_) return;

    float c = g_cos[(size_t)(NSITE - 1) * B_ + warp];
    float s = g_sin[(size_t)(NSITE - 1) * B_ + warp];
    const float* L = g_left[cur] + (size_t)warp * D_;

    float sum = 0.0f;
#pragma unroll
    for (int i = 0; i < 4; i++) {
        int l = lane + i * 32;
        sum += L[l] * (last[2 * l] * c + last[2 * l + 1] * s);
    }
#pragma unroll
    for (int o = 16; o; o >>= 1)
        sum += __shfl_xor_sync(0xffffffffu, sum, o);
    sum = __shfl_sync(0xffffffffu, sum, 0);

    if (lane < OUT_)
        out[(size_t)warp * OUT_ + lane] = sum * w[lane] + bias[lane];
}

// ==========================================================================
// Launch: 1 + 1 + 254 + 1 = 257 graph nodes, all plain kernel launches.
// ==========================================================================
extern "C" void kernel_launch(void* const* d_in, const int* in_sizes, int n_in,
                              void* d_out, int out_size) {
    const float* x     = (const float*)d_in[0];  // [B, N]
    const float* first = (const float*)d_in[1];  // [1, 2, D]
    const float* mid   = (const float*)d_in[2];  // [N-2, D, 2, D]
    const float* last  = (const float*)d_in[3];  // [D, 2, 1]
    const float* w     = (const float*)d_in[4];  // [OUT, 1]
    const float* bias  = (const float*)d_in[5];  // [OUT]
    float* out = (float*)d_out;                  // [B, OUT]

    // Opt-in to >48KB dynamic smem (idempotent, host-side, capture-safe).
    cudaFuncSetAttribute(step_kernel,
                         cudaFuncAttributeMaxDynamicSharedMemorySize,
                         STEP_SMEM_BYTES);

    phi_kernel<<<B_ / 8, 256>>>(x);
    left0_kernel<<<B_, D_>>>(first);

    int cur = 0;
    for (int m = 0; m < NSITE - 2; m++) {
        step_kernel<<<dim3(64, 2), 256, STEP_SMEM_BYTES>>>(mid, m, cur);
        cur ^= 1;
    }

    final_kernel<<<B_ / 8, 256>>>(last, w, bias, out, cur);
}